// round 3
// baseline (speedup 1.0000x reference)
#include <cuda_runtime.h>

typedef unsigned long long ull;

#define WIDTH     16384
#define WOUT      16353      // WIDTH - 32 + 1
#define NROWS     1024       // B*H = 16*64
#define FILTER_L  32
#define LUT_N     4096
#define LUT_SCALE 256.0f     // entries per unit of |x|; covers mag in [0,16)
#define TILE      2048
#define THREADS   256
#define RPT       8          // outputs per thread (TILE/THREADS)
#define SG_N      2080       // TILE + 31 halo, rounded to multiple of 16
#define OUT_SCALE 0.17782794100389226f  // sqrt(10^(-15/10))

__device__ float2 d_lut[LUT_N];

// ---------------- helpers ----------------
__device__ __forceinline__ int swz(int i) { return i ^ ((i >> 4) & 0xF); }

__device__ __forceinline__ ull pack2(float lo, float hi) {
    ull v;
    asm("mov.b64 %0, {%1, %2};" : "=l"(v) : "f"(lo), "f"(hi));
    return v;
}

__device__ __forceinline__ void unpack2(ull v, float& lo, float& hi) {
    asm("mov.b64 {%0, %1}, %2;" : "=f"(lo), "=f"(hi) : "l"(v));
}

__device__ __forceinline__ ull fma2(ull a, ull b, ull c) {
    ull d;
    asm("fma.rn.f32x2 %0, %1, %2, %3;" : "=l"(d) : "l"(a), "l"(b), "l"(c));
    return d;
}

__device__ __forceinline__ float fast_sqrt(float x) {
    float r;
    asm("sqrt.approx.f32 %0, %1;" : "=f"(r) : "f"(x));
    return r;
}

// ---------------- LUT build: g(m) = OUT_SCALE * (sum_o w2[o]*tanh(w1[o]*m)) / m ----------------
__global__ void build_lut_kernel(const float* __restrict__ w1,
                                 const float* __restrict__ w2) {
    int i = blockIdx.x * blockDim.x + threadIdx.x;
    if (i >= LUT_N) return;

    float a[8], b[8];
#pragma unroll
    for (int o = 0; o < 8; o++) { a[o] = w1[o]; b[o] = w2[o]; }

    auto gf = [&](float m) -> float {
        if (m <= 0.0f) {
            float s = 0.0f;
#pragma unroll
            for (int o = 0; o < 8; o++) s += b[o] * a[o];   // lim h(m)/m
            return s;
        }
        float s = 0.0f;
#pragma unroll
        for (int o = 0; o < 8; o++) s += b[o] * tanhf(a[o] * m);
        return s / m;
    };

    float m0 = (float)i * (1.0f / LUT_SCALE);
    float g0 = gf(m0);
    float g1 = gf(m0 + (1.0f / LUT_SCALE));
    d_lut[i] = make_float2(OUT_SCALE * g0, OUT_SCALE * (g1 - g0));
}

// ---------------- fused envelope-MLP + complex FIR ----------------
__global__ void __launch_bounds__(THREADS)
fused_fir_kernel(const float* __restrict__ xr, const float* __restrict__ xi,
                 const float* __restrict__ kr, const float* __restrict__ ki,
                 float* __restrict__ out) {
    __shared__ float2 sg[SG_N];           // swizzled (gr, gi) pairs
    __shared__ ull skr[FILTER_L];         // (kr, kr) packed
    __shared__ ull ski[FILTER_L];         // (ki, ki) packed

    const int tid = threadIdx.x;
    const int row = blockIdx.y;
    const int w0  = blockIdx.x * TILE;

    if (tid < FILTER_L) {
        float a = kr[tid];
        float b = ki[tid];
        skr[tid] = pack2(a, a);
        ski[tid] = pack2(b, b);
    }

    const float* __restrict__ xrp = xr + (size_t)row * WIDTH + w0;
    const float* __restrict__ xip = xi + (size_t)row * WIDTH + w0;
    const int L = min(TILE + FILTER_L - 1, WIDTH - w0);  // valid inputs this tile

    // preprocess: mag -> LUT -> g, store (g*xr, g*xi) swizzled into shared
    for (int idx = tid; idx < SG_N; idx += THREADS) {
        float gr = 0.0f, gi = 0.0f;
        if (idx < L) {
            float a = __ldg(xrp + idx);
            float b = __ldg(xip + idx);
            float s = fmaf(a, a, b * b);
            float m = fast_sqrt(s);
            float fi = fminf(m * LUT_SCALE, 4095.0f);
            int   ii = (int)fi;
            float fr = fi - (float)ii;
            float2 e = __ldg(&d_lut[ii]);
            float g = fmaf(e.y, fr, e.x);
            gr = g * a;
            gi = g * b;
        }
        sg[swz(idx)] = make_float2(gr, gi);
    }
    __syncthreads();

    // FIR: each thread produces RPT consecutive outputs with f32x2 FMAs
    const int base = tid * RPT;

    ull acca[RPT], accb[RPT], Wn[RPT];
#pragma unroll
    for (int r = 0; r < RPT; r++) { acca[r] = 0ull; accb[r] = 0ull; }
#pragma unroll
    for (int r = 0; r < RPT; r++)
        Wn[r] = *reinterpret_cast<const ull*>(&sg[swz(base + r)]);

#pragma unroll
    for (int t = 0; t < FILTER_L; t++) {
        ull k2 = skr[t];
        ull q2 = ski[t];
#pragma unroll
        for (int r = 0; r < RPT; r++) {
            ull v = Wn[(t + r) & (RPT - 1)];
            acca[r] = fma2(v, k2, acca[r]);   // (sum kr*gr, sum kr*gi)
            accb[r] = fma2(v, q2, accb[r]);   // (sum ki*gr, sum ki*gi)
        }
        if (t < FILTER_L - 1)
            Wn[t & (RPT - 1)] =
                *reinterpret_cast<const ull*>(&sg[swz(base + t + RPT)]);
    }

    float2* op = reinterpret_cast<float2*>(out) + (size_t)row * WOUT + w0 + base;
    const int rem = WOUT - (w0 + base);   // may be <= 0 for tail threads
#pragma unroll
    for (int r = 0; r < RPT; r++) {
        if (r < rem) {
            float ax, ay, bx, by;
            unpack2(acca[r], ax, ay);
            unpack2(accb[r], bx, by);
            op[r] = make_float2(ax - by, ay + bx);  // (yr, yi), scale folded in LUT
        }
    }
}

extern "C" void kernel_launch(void* const* d_in, const int* in_sizes, int n_in,
                              void* d_out, int out_size) {
    const float* xr = (const float*)d_in[0];   // x_real  [16,64,16384,1]
    const float* xi = (const float*)d_in[1];   // x_imag
    const float* w1 = (const float*)d_in[2];   // w_nl1 [8]
    const float* w2 = (const float*)d_in[3];   // w_nl2 [8]
    const float* kr = (const float*)d_in[4];   // w_lin_real [32]
    const float* ki = (const float*)d_in[5];   // w_lin_imag [32]
    float* out = (float*)d_out;

    build_lut_kernel<<<(LUT_N + 255) / 256, 256>>>(w1, w2);

    dim3 grid((WOUT + TILE - 1) / TILE, NROWS);   // (8, 1024)
    fused_fir_kernel<<<grid, THREADS>>>(xr, xi, kr, ki, out);
}

// round 4
// speedup vs baseline: 1.8239x; 1.8239x over previous
#include <cuda_runtime.h>

typedef unsigned long long ull;

#define WIDTH     16384
#define WOUT      16353      // WIDTH - 32 + 1
#define NROWS     1024       // B*H = 16*64
#define FILTER_L  32
#define LUT_N     4096
#define LUT_SCALE 256.0f     // entries per unit of |x|; covers mag in [0,16)
#define TILE      1024
#define THREADS   256
#define RPT       4          // outputs per thread (TILE/THREADS)
#define SG_N      1056       // TILE + 31 halo, rounded to multiple of 16
#define NGROUPS   (SG_N/4)   // 264 float4-groups
#define OUT_SCALE 0.17782794100389226f  // sqrt(10^(-15/10))

__device__ float2 d_lut[LUT_N];

// ---------------- helpers ----------------
__device__ __forceinline__ int swz(int i) { return i ^ ((i >> 4) & 0xF); }

__device__ __forceinline__ ull pack2(float lo, float hi) {
    ull v;
    asm("mov.b64 %0, {%1, %2};" : "=l"(v) : "f"(lo), "f"(hi));
    return v;
}

__device__ __forceinline__ void unpack2(ull v, float& lo, float& hi) {
    asm("mov.b64 {%0, %1}, %2;" : "=f"(lo), "=f"(hi) : "l"(v));
}

__device__ __forceinline__ ull fma2(ull a, ull b, ull c) {
    ull d;
    asm("fma.rn.f32x2 %0, %1, %2, %3;" : "=l"(d) : "l"(a), "l"(b), "l"(c));
    return d;
}

__device__ __forceinline__ float fast_sqrt(float x) {
    float r;
    asm("sqrt.approx.f32 %0, %1;" : "=f"(r) : "f"(x));
    return r;
}

// ---------------- LUT build: g(m) = OUT_SCALE * (sum_o w2[o]*tanh(w1[o]*m)) / m ----------------
__global__ void build_lut_kernel(const float* __restrict__ w1,
                                 const float* __restrict__ w2) {
    int i = blockIdx.x * blockDim.x + threadIdx.x;
    if (i >= LUT_N) return;

    float a[8], b[8];
#pragma unroll
    for (int o = 0; o < 8; o++) { a[o] = w1[o]; b[o] = w2[o]; }

    auto gf = [&](float m) -> float {
        if (m <= 0.0f) {
            float s = 0.0f;
#pragma unroll
            for (int o = 0; o < 8; o++) s += b[o] * a[o];   // lim h(m)/m
            return s;
        }
        float s = 0.0f;
#pragma unroll
        for (int o = 0; o < 8; o++) s += b[o] * tanhf(a[o] * m);
        return s / m;
    };

    float m0 = (float)i * (1.0f / LUT_SCALE);
    float g0 = gf(m0);
    float g1 = gf(m0 + (1.0f / LUT_SCALE));
    d_lut[i] = make_float2(OUT_SCALE * g0, OUT_SCALE * (g1 - g0));
}

// ---------------- fused envelope-MLP + complex FIR ----------------
__global__ void __launch_bounds__(THREADS, 6)
fused_fir_kernel(const float* __restrict__ xr, const float* __restrict__ xi,
                 const float* __restrict__ kr, const float* __restrict__ ki,
                 float* __restrict__ out) {
    __shared__ float2 sg[SG_N];           // swizzled (gr, gi) pairs
    __shared__ ull skr[FILTER_L];         // (kr, kr) packed
    __shared__ ull ski[FILTER_L];         // (ki, ki) packed

    const int tid = threadIdx.x;
    const int row = blockIdx.y;
    const int w0  = blockIdx.x * TILE;

    if (tid < FILTER_L) {
        float a = kr[tid];
        float b = ki[tid];
        skr[tid] = pack2(a, a);
        ski[tid] = pack2(b, b);
    }

    const float* __restrict__ xrp = xr + (size_t)row * WIDTH + w0;
    const float* __restrict__ xip = xi + (size_t)row * WIDTH + w0;
    const int L = min(TILE + FILTER_L - 1, WIDTH - w0);  // valid inputs this tile

    // preprocess: float4 loads, mag -> LUT -> g, store (g*xr, g*xi) swizzled into shared
    for (int g4 = tid; g4 < NGROUPS; g4 += THREADS) {
        const int idx = g4 * 4;
        float ar[4], ai[4];
        if (idx + 3 < L) {
            float4 vr = *reinterpret_cast<const float4*>(xrp + idx);
            float4 vi = *reinterpret_cast<const float4*>(xip + idx);
            ar[0] = vr.x; ar[1] = vr.y; ar[2] = vr.z; ar[3] = vr.w;
            ai[0] = vi.x; ai[1] = vi.y; ai[2] = vi.z; ai[3] = vi.w;
        } else {
#pragma unroll
            for (int k = 0; k < 4; k++) {
                ar[k] = (idx + k < L) ? __ldg(xrp + idx + k) : 0.0f;
                ai[k] = (idx + k < L) ? __ldg(xip + idx + k) : 0.0f;
            }
        }
#pragma unroll
        for (int k = 0; k < 4; k++) {
            float a = ar[k], b = ai[k];
            float s = fmaf(a, a, b * b);
            float m = fast_sqrt(s);
            float fi = fminf(m * LUT_SCALE, 4095.0f);
            int   ii = (int)fi;
            float fr = fi - (float)ii;
            float2 e = __ldg(&d_lut[ii]);
            float g = fmaf(e.y, fr, e.x);
            sg[swz(idx + k)] = make_float2(g * a, g * b);
        }
    }
    __syncthreads();

    // FIR: each thread produces RPT consecutive outputs with f32x2 FMAs
    const int base = tid * RPT;

    ull acca[RPT], accb[RPT], Wn[RPT];
#pragma unroll
    for (int r = 0; r < RPT; r++) { acca[r] = 0ull; accb[r] = 0ull; }
#pragma unroll
    for (int r = 0; r < RPT; r++)
        Wn[r] = *reinterpret_cast<const ull*>(&sg[swz(base + r)]);

#pragma unroll
    for (int t = 0; t < FILTER_L; t++) {
        ull k2 = skr[t];
        ull q2 = ski[t];
#pragma unroll
        for (int r = 0; r < RPT; r++) {
            ull v = Wn[(t + r) & (RPT - 1)];
            acca[r] = fma2(v, k2, acca[r]);   // (sum kr*gr, sum kr*gi)
            accb[r] = fma2(v, q2, accb[r]);   // (sum ki*gr, sum ki*gi)
        }
        if (t < FILTER_L - 1)
            Wn[t & (RPT - 1)] =
                *reinterpret_cast<const ull*>(&sg[swz(base + t + RPT)]);
    }

    float2* op = reinterpret_cast<float2*>(out) + (size_t)row * WOUT + w0 + base;
    const int rem = WOUT - (w0 + base);   // may be <= 0 for tail threads
#pragma unroll
    for (int r = 0; r < RPT; r++) {
        if (r < rem) {
            float ax, ay, bx, by;
            unpack2(acca[r], ax, ay);
            unpack2(accb[r], bx, by);
            op[r] = make_float2(ax - by, ay + bx);  // (yr, yi), scale folded in LUT
        }
    }
}

extern "C" void kernel_launch(void* const* d_in, const int* in_sizes, int n_in,
                              void* d_out, int out_size) {
    const float* xr = (const float*)d_in[0];   // x_real  [16,64,16384,1]
    const float* xi = (const float*)d_in[1];   // x_imag
    const float* w1 = (const float*)d_in[2];   // w_nl1 [8]
    const float* w2 = (const float*)d_in[3];   // w_nl2 [8]
    const float* kr = (const float*)d_in[4];   // w_lin_real [32]
    const float* ki = (const float*)d_in[5];   // w_lin_imag [32]
    float* out = (float*)d_out;

    build_lut_kernel<<<(LUT_N + 255) / 256, 256>>>(w1, w2);

    dim3 grid((WOUT + TILE - 1) / TILE, NROWS);   // (16, 1024)
    fused_fir_kernel<<<grid, THREADS>>>(xr, xi, kr, ki, out);
}